// round 12
// baseline (speedup 1.0000x reference)
#include <cuda_runtime.h>
#include <cuda_fp16.h>
#include <cstdint>

// Problem constants
#define Bsz 4096
#define Vn  50
#define Fn  15
#define Hn  256
#define Gn  1024   // 4*H

// ---------------- scratch (static device globals; no allocation) ----------
__device__ float g_c1 [Bsz * Hn];
__device__ float g_c2 [Bsz * Hn];
__device__ float g_h1f[Bsz * Hn];
__device__ float g_h2f[Bsz * Hn];
__device__ __half g_h1hi[2][Bsz * Hn];
__device__ __half g_h1lo[2][Bsz * Hn];
__device__ __half g_h2hi[2][Bsz * Hn];
__device__ __half g_h2lo[2][Bsz * Hn];
__device__ __half g_w1hi[Gn * Hn], g_w1lo[Gn * Hn];
__device__ __half g_w2hi[Gn * Hn], g_w2lo[Gn * Hn];
__device__ __half g_wx1hi[Gn * 16], g_wx1lo[Gn * 16];
__device__ __half g_wx2hi[Gn * 16], g_wx2lo[Gn * 16];
__device__ __half g_xshi[Vn * Bsz * 16], g_xslo[Vn * Bsz * 16];
__device__ float g_badd1[Gn];
__device__ float g_m1[Bsz * 1024];
__device__ float g_m2[Bsz * 1024];
__device__ float g_m3[Bsz * 512];
__device__ float g_m4[Bsz * 256];
__device__ float g_pre2[Bsz * Gn];

typedef unsigned long long ull;

__device__ __forceinline__ void dup2(ull& d, float s) {
    asm("mov.b64 %0,{%1,%1};" : "=l"(d) : "f"(s));
}
__device__ __forceinline__ void ffma2(ull& d, ull a, ull b) {
    asm("fma.rn.f32x2 %0,%1,%2,%0;" : "+l"(d) : "l"(a), "l"(b));
}
__device__ __forceinline__ float2 u2f(ull u) {
    float2 f; asm("mov.b64 {%0,%1},%2;" : "=f"(f.x), "=f"(f.y) : "l"(u)); return f;
}
// Fast-math gates (validated round 11: rel_err 7e-6 total).
__device__ __forceinline__ float fsig(float x) {
    return __fdividef(1.0f, 1.0f + __expf(-x));
}
__device__ __forceinline__ float ftanh(float x) {
    return 1.0f - __fdividef(2.0f, __expf(2.0f * x) + 1.0f);
}

// ---------------- warp-MMA helpers ------------------------------------------
__device__ __forceinline__ uint32_t smem_u32(const void* p) {
    uint32_t a;
    asm("{ .reg .u64 t; cvta.to.shared.u64 t, %1; cvt.u32.u64 %0, t; }" : "=r"(a) : "l"(p));
    return a;
}
__device__ __forceinline__ void ldm_x4(uint32_t* r, uint32_t addr) {
    asm volatile("ldmatrix.sync.aligned.m8n8.x4.shared.b16 {%0,%1,%2,%3}, [%4];"
        : "=r"(r[0]), "=r"(r[1]), "=r"(r[2]), "=r"(r[3]) : "r"(addr));
}
__device__ __forceinline__ void ldm_x2(uint32_t* r, uint32_t addr) {
    asm volatile("ldmatrix.sync.aligned.m8n8.x2.shared.b16 {%0,%1}, [%2];"
        : "=r"(r[0]), "=r"(r[1]) : "r"(addr));
}
__device__ __forceinline__ void mma16816(float* d, const uint32_t* a, const uint32_t* b) {
    asm volatile("mma.sync.aligned.m16n8k16.row.col.f32.f16.f16.f32 "
        "{%0,%1,%2,%3},{%4,%5,%6,%7},{%8,%9},{%0,%1,%2,%3};"
        : "+f"(d[0]), "+f"(d[1]), "+f"(d[2]), "+f"(d[3])
        : "r"(a[0]), "r"(a[1]), "r"(a[2]), "r"(a[3]), "r"(b[0]), "r"(b[1]));
}
__device__ __forceinline__ void cp16(uint32_t d, const void* s) {
    asm volatile("cp.async.cg.shared.global [%0], [%1], 16;" :: "r"(d), "l"(s));
}
#define CP_COMMIT() asm volatile("cp.async.commit_group;" ::: "memory")
#define CP_WAIT0()  asm volatile("cp.async.wait_group 0;" ::: "memory")

#define LDP 24   // 48 B/row: 16B-aligned, conflict-free ldmatrix

// ---------------- fused LSTM step (fp16-split MMA, pass-OUTER order) --------
// KEY CHANGE vs round 11: the 3 split passes (hi*hi, hi*lo, lo*hi) are the
// OUTER loop per K-chunk, so consecutive MMAs on the same accumulator are 8
// apart (was back-to-back) -> HMMA latency hidden by independent MMAs.
// Fragments reloaded per pass (live regs ~73, fits 85-reg cap w/ headroom).
template <int USE_PRE2, int WRITE_HF, int WRITE_SPLIT>
__global__ void __launch_bounds__(256, 3) lstm_step_mma(
    const __half* __restrict__ hA_hi, const __half* __restrict__ hA_lo,
    const __half* __restrict__ W_hi,  const __half* __restrict__ W_lo,
    const __half* __restrict__ Wx_hi, const __half* __restrict__ Wx_lo,
    const __half* __restrict__ xs_hi, const __half* __restrict__ xs_lo,
    const float* __restrict__ preact,
    float* __restrict__ cSt, float* __restrict__ hF,
    __half* __restrict__ hO_hi, __half* __restrict__ hO_lo)
{
    __shared__ __align__(16) __half shA[2][2][64 * LDP];    // [buf][hi/lo]
    __shared__ __align__(16) __half shW[2][2][128 * LDP];

    const int tid  = threadIdx.x;
    const int wid  = tid >> 5;
    const int lane = tid & 31;
    const int n0 = blockIdx.x * 128;   // remapped gate-col base
    const int m0 = blockIdx.y * 64;    // batch-row base
    const int wm0 = (wid & 1) * 32;
    const int wn0 = (wid >> 1) * 32;

    float acc[2][4][4];
#pragma unroll
    for (int i = 0; i < 2; i++)
#pragma unroll
        for (int j = 0; j < 4; j++)
#pragma unroll
            for (int k = 0; k < 4; k++) acc[i][j][k] = 0.f;

    // cp.async staging
    const int arow = tid >> 2;
    const int ahl  = (tid >> 1) & 1;
    const int ablk = tid & 1;
    const uint32_t dOff = (uint32_t)(arow * LDP + ablk * 8) * 2;

    const __half* baseA  = (ahl ? hA_lo : hA_hi) + (size_t)(m0 + arow) * Hn + ablk * 8;
    const __half* baseW1 = (ahl ? W_lo  : W_hi)  + (size_t)(n0 + arow) * Hn + ablk * 8;
    const __half* baseW2 = (ahl ? W_lo  : W_hi)  + (size_t)(n0 + arow + 64) * Hn + ablk * 8;
    const __half* baseAx  = (ahl ? xs_lo  : xs_hi)  + (size_t)(m0 + arow) * 16 + ablk * 8;
    const __half* baseWx1 = (ahl ? Wx_lo : Wx_hi) + (size_t)(n0 + arow) * 16 + ablk * 8;
    const __half* baseWx2 = (ahl ? Wx_lo : Wx_hi) + (size_t)(n0 + arow + 64) * 16 + ablk * 8;

    const uint32_t sAh[2] = { smem_u32(&shA[0][0][0]), smem_u32(&shA[1][0][0]) };
    const uint32_t sAl[2] = { smem_u32(&shA[0][1][0]), smem_u32(&shA[1][1][0]) };
    const uint32_t sWh[2] = { smem_u32(&shW[0][0][0]), smem_u32(&shW[1][0][0]) };
    const uint32_t sWl[2] = { smem_u32(&shW[0][1][0]), smem_u32(&shW[1][1][0]) };

    auto stage = [&](int buf, int c) {
        const __half *pA, *pW1, *pW2;
        if (c < 16) {
            pA  = baseA  + c * 16;
            pW1 = baseW1 + c * 16;
            pW2 = baseW2 + c * 16;
        } else {
            pA = baseAx; pW1 = baseWx1; pW2 = baseWx2;
        }
        uint32_t da = (ahl ? sAl[buf] : sAh[buf]) + dOff;
        uint32_t dw = (ahl ? sWl[buf] : sWh[buf]) + dOff;
        cp16(da, pA);
        cp16(dw, pW1);
        cp16(dw + 64 * LDP * 2, pW2);
    };

    // ldmatrix lane addressing
    const int l15 = lane & 15;
    const uint32_t aoff = ((uint32_t)((wm0 + l15) * LDP + (lane >> 4) * 8)) * 2;
    const int bl = lane & 7;
    const uint32_t boffbase = ((uint32_t)((wn0 + bl) * LDP + ((lane >> 3) & 1) * 8)) * 2;

    // ---- preload chunk 0 ----
    stage(0, 0);
    CP_COMMIT();
    CP_WAIT0();
    __syncthreads();

    for (int c = 0; c < 17; c++) {
        if (c < 16) {
            stage((c + 1) & 1, c + 1);
            CP_COMMIT();
        }
        const int cb = c & 1;

        // ---- 3 passes OUTER: t=0 ah*bh, t=1 ah*blo, t=2 al*bh ----
#pragma unroll
        for (int t = 0; t < 3; t++) {
            const uint32_t sa = (t == 2) ? sAl[cb] : sAh[cb];
            const uint32_t sw = (t == 1) ? sWl[cb] : sWh[cb];
            uint32_t bf[4][2];
#pragma unroll
            for (int nf = 0; nf < 4; nf++)
                ldm_x2(bf[nf], sw + boffbase + (uint32_t)(nf * 8 * LDP) * 2);
            uint32_t af[2][4];
#pragma unroll
            for (int mt = 0; mt < 2; mt++)
                ldm_x4(af[mt], sa + aoff + (uint32_t)(mt * 16 * LDP) * 2);
            // 8 MMAs per pass, all on DISTINCT accumulators
#pragma unroll
            for (int mt = 0; mt < 2; mt++)
#pragma unroll
                for (int nf = 0; nf < 4; nf++)
                    mma16816(acc[mt][nf], af[mt], bf[nf]);
        }

        if (c < 16) {
            CP_WAIT0();
            __syncthreads();
        }
    }

    // ---- epilogue: combine gate pairs via shfl, LSTM cell update ----
    const bool odd = (lane & 1);
#pragma unroll
    for (int mt = 0; mt < 2; mt++) {
#pragma unroll
        for (int nf = 0; nf < 4; nf++) {
            float c0 = acc[mt][nf][0], c1 = acc[mt][nf][1];
            float c2 = acc[mt][nf][2], c3 = acc[mt][nf][3];
            float v0 = odd ? c0 : c2;
            float v1 = odd ? c1 : c3;
            float r0 = __shfl_xor_sync(0xffffffffu, v0, 1);
            float r1 = __shfl_xor_sync(0xffffffffu, v1, 1);
            float gi = odd ? r0 : c0;
            float gf = odd ? r1 : c1;
            float gg = odd ? c2 : r0;
            float go = odd ? c3 : r1;
            int m = m0 + wm0 + mt * 16 + (lane >> 2) + (odd ? 8 : 0);
            int nb = n0 + wn0 + nf * 8 + ((lane >> 1) & 1) * 4;   // = 4*u
            float4 p = USE_PRE2 ? *(const float4*)(preact + (size_t)m * Gn + nb)
                                : *(const float4*)(preact + nb);
            gi += p.x; gf += p.y; gg += p.z; go += p.w;
            int u = nb >> 2;
            size_t ci = (size_t)m * Hn + u;
            float cold = cSt[ci];
            float iv = fsig(gi), fv = fsig(gf);
            float gv = ftanh(gg), ov = fsig(go);
            float cn = fv * cold + iv * gv;
            cSt[ci] = cn;
            float h = ov * ftanh(cn);
            if (WRITE_HF) hF[ci] = h;
            if (WRITE_SPLIT) {
                __half hh = __float2half_rn(h);
                hO_hi[ci] = hh;
                hO_lo[ci] = __float2half_rn(h - __half2float(hh));
            }
        }
    }
}

// ---------------- prep kernels ----------------------------------------------
__global__ void zero_states_kernel() {
    int idx = blockIdx.x * blockDim.x + threadIdx.x;
    if (idx < Bsz * Hn) {
        g_c1[idx] = 0.f; g_c2[idx] = 0.f;
        __half z = __float2half_rn(0.f);
        g_h1hi[0][idx] = z; g_h1lo[0][idx] = z;
        g_h2hi[0][idx] = z; g_h2lo[0][idx] = z;
    }
}

__global__ void prep_w_kernel(const float* __restrict__ whh1, const float* __restrict__ wih1,
                              const float* __restrict__ b1i,  const float* __restrict__ b1h,
                              const float* __restrict__ whh2, const float* __restrict__ wih2) {
    int idx = blockIdx.x * blockDim.x + threadIdx.x;
    if (idx >= Gn * Hn) return;
    int n = idx >> 8;
    int k = idx & 255;
    int orig = ((n & 3) << 8) | (n >> 2);
    float v1 = whh1[orig * Hn + k];
    __half h1 = __float2half_rn(v1);
    g_w1hi[idx] = h1;
    g_w1lo[idx] = __float2half_rn(v1 - __half2float(h1));
    float v2 = whh2[orig * Hn + k];
    __half h2 = __float2half_rn(v2);
    g_w2hi[idx] = h2;
    g_w2lo[idx] = __float2half_rn(v2 - __half2float(h2));
    if (k < 16) {
        float x1 = (k < Fn) ? wih1[orig * Fn + k] : 0.f;
        __half xh1 = __float2half_rn(x1);
        g_wx1hi[n * 16 + k] = xh1;
        g_wx1lo[n * 16 + k] = __float2half_rn(x1 - __half2float(xh1));
        float x2 = (k < Fn) ? wih2[orig * 271 + k] : 0.f;
        __half xh2 = __float2half_rn(x2);
        g_wx2hi[n * 16 + k] = xh2;
        g_wx2lo[n * 16 + k] = __float2half_rn(x2 - __half2float(xh2));
    }
    if (k == 0) g_badd1[n] = b1i[orig] + b1h[orig];
}

__global__ void prep_x_kernel(const float* __restrict__ state) {
    int idx = blockIdx.x * blockDim.x + threadIdx.x;
    if (idx >= Vn * Bsz * 16) return;
    int k = idx & 15;
    int b = (idx >> 4) & (Bsz - 1);
    int v = idx >> 16;
    float val = (k < Fn) ? state[(size_t)b * (Vn * Fn) + v * Fn + k] : 0.f;
    __half h = __float2half_rn(val);
    g_xshi[idx] = h;
    g_xslo[idx] = __float2half_rn(val - __half2float(h));
}

// ---------------- fp32 gemm (MLP + pre2), proven in round 5 -----------------
template <int EPI, int REMAP, int W4>
__global__ void __launch_bounds__(256, 2) gemm3(
    const float* __restrict__ A,  int lda,
    const float* __restrict__ W,  int ldw, int K,
    const float* __restrict__ b1, const float* __restrict__ b2,
    float* __restrict__ C, int N)
{
    __shared__ float As[2][16][128];
    __shared__ float Bs[2][16][128];

    const int tid = threadIdx.x;
    const int tx = tid & 15;
    const int ty = tid >> 4;
    const int m0 = blockIdx.y * 128;
    const int n0 = blockIdx.x * 128;

    const int lr = tid >> 1;
    const int lc = (tid & 1) * 8;
    const int gn = n0 + lr;
    const int wrow = REMAP ? (((gn & 3) << 8) | (gn >> 2)) : gn;
    const float* Ap = A + (size_t)(m0 + lr) * lda + lc;
    const float* Wp = W + (size_t)wrow * ldw + lc;

    ull acc[8][4];
#pragma unroll
    for (int i = 0; i < 8; i++)
#pragma unroll
        for (int j = 0; j < 4; j++) acc[i][j] = 0ull;

    {
        float4 a0 = *(const float4*)Ap;
        float4 a1 = *(const float4*)(Ap + 4);
        float4 w0, w1;
        if (W4) { w0 = *(const float4*)Wp; w1 = *(const float4*)(Wp + 4); }
        else {
            w0 = make_float4(Wp[0], Wp[1], Wp[2], Wp[3]);
            w1 = make_float4(Wp[4], Wp[5], Wp[6], Wp[7]);
        }
        As[0][lc + 0][lr] = a0.x; As[0][lc + 1][lr] = a0.y;
        As[0][lc + 2][lr] = a0.z; As[0][lc + 3][lr] = a0.w;
        As[0][lc + 4][lr] = a1.x; As[0][lc + 5][lr] = a1.y;
        As[0][lc + 6][lr] = a1.z; As[0][lc + 7][lr] = a1.w;
        Bs[0][lc + 0][lr] = w0.x; Bs[0][lc + 1][lr] = w0.y;
        Bs[0][lc + 2][lr] = w0.z; Bs[0][lc + 3][lr] = w0.w;
        Bs[0][lc + 4][lr] = w1.x; Bs[0][lc + 5][lr] = w1.y;
        Bs[0][lc + 6][lr] = w1.z; Bs[0][lc + 7][lr] = w1.w;
    }
    __syncthreads();

    int cur = 0;
    for (int k0 = 0; k0 < K; k0 += 16) {
        const bool more = (k0 + 16) < K;
        float4 pa0, pa1, pw0, pw1;
        if (more) {
            pa0 = *(const float4*)(Ap + k0 + 16);
            pa1 = *(const float4*)(Ap + k0 + 20);
            const float* wq = Wp + k0 + 16;
            if (W4) { pw0 = *(const float4*)wq; pw1 = *(const float4*)(wq + 4); }
            else {
                pw0 = make_float4(wq[0], wq[1], wq[2], wq[3]);
                pw1 = make_float4(wq[4], wq[5], wq[6], wq[7]);
            }
        }
#pragma unroll
        for (int kk = 0; kk < 16; kk++) {
            float4 a0 = *(const float4*)&As[cur][kk][ty * 4];
            float4 a1 = *(const float4*)&As[cur][kk][64 + ty * 4];
            ulonglong2 bq0 = *(const ulonglong2*)&Bs[cur][kk][tx * 4];
            ulonglong2 bq1 = *(const ulonglong2*)&Bs[cur][kk][64 + tx * 4];
            float ar[8] = {a0.x, a0.y, a0.z, a0.w, a1.x, a1.y, a1.z, a1.w};
#pragma unroll
            for (int i = 0; i < 8; i++) {
                ull aa; dup2(aa, ar[i]);
                ffma2(acc[i][0], aa, bq0.x);
                ffma2(acc[i][1], aa, bq0.y);
                ffma2(acc[i][2], aa, bq1.x);
                ffma2(acc[i][3], aa, bq1.y);
            }
        }
        if (more) {
            int nx = cur ^ 1;
            As[nx][lc + 0][lr] = pa0.x; As[nx][lc + 1][lr] = pa0.y;
            As[nx][lc + 2][lr] = pa0.z; As[nx][lc + 3][lr] = pa0.w;
            As[nx][lc + 4][lr] = pa1.x; As[nx][lc + 5][lr] = pa1.y;
            As[nx][lc + 6][lr] = pa1.z; As[nx][lc + 7][lr] = pa1.w;
            Bs[nx][lc + 0][lr] = pw0.x; Bs[nx][lc + 1][lr] = pw0.y;
            Bs[nx][lc + 2][lr] = pw0.z; Bs[nx][lc + 3][lr] = pw0.w;
            Bs[nx][lc + 4][lr] = pw1.x; Bs[nx][lc + 5][lr] = pw1.y;
            Bs[nx][lc + 6][lr] = pw1.z; Bs[nx][lc + 7][lr] = pw1.w;
        }
        __syncthreads();
        cur ^= 1;
    }

    float add[8];
#pragma unroll
    for (int j = 0; j < 8; j++) {
        int n = n0 + ((j < 4) ? (4 * tx + j) : (64 + 4 * tx + (j - 4)));
        int rn = REMAP ? (((n & 3) << 8) | (n >> 2)) : n;
        float t = 0.f;
        if (b1) t += b1[rn];
        if (b2) t += b2[rn];
        add[j] = t;
    }
#pragma unroll
    for (int i = 0; i < 8; i++) {
        int m = m0 + ((i < 4) ? (4 * ty + i) : (64 + 4 * ty + (i - 4)));
        float o[8];
#pragma unroll
        for (int j4 = 0; j4 < 4; j4++) {
            float2 f = u2f(acc[i][j4]);
            o[2 * j4]     = f.x + add[2 * j4];
            o[2 * j4 + 1] = f.y + add[2 * j4 + 1];
        }
        if (EPI == 1) {
#pragma unroll
            for (int j = 0; j < 8; j++) o[j] = fmaxf(o[j], 0.f);
        }
        *(float4*)(C + (size_t)m * N + n0 + 4 * tx)      = make_float4(o[0], o[1], o[2], o[3]);
        *(float4*)(C + (size_t)m * N + n0 + 64 + 4 * tx) = make_float4(o[4], o[5], o[6], o[7]);
    }
}

// ---------------- pi head ---------------------------------------------------
__global__ void pi_kernel(const float* __restrict__ h2,
                          const float* __restrict__ piW,
                          const float* __restrict__ pib,
                          float* __restrict__ out, int v) {
    int gw = (blockIdx.x * blockDim.x + threadIdx.x) >> 5;
    int lane = threadIdx.x & 31;
    if (gw >= Bsz) return;
    const float* hr = h2 + (size_t)gw * Hn;
    float s = 0.f;
#pragma unroll
    for (int k = lane; k < Hn; k += 32) s += hr[k] * piW[k];
#pragma unroll
    for (int off = 16; off > 0; off >>= 1)
        s += __shfl_down_sync(0xffffffffu, s, off);
    if (lane == 0)
        out[(size_t)gw * Vn + v] = ftanh(s + pib[0]);
}

// ---------------- launch ----------------------------------------------------
extern "C" void kernel_launch(void* const* d_in, const int* in_sizes, int n_in,
                              void* d_out, int out_size) {
    const float* state  = (const float*)d_in[0];
    const float* l1_Wih = (const float*)d_in[1];
    const float* l1_Whh = (const float*)d_in[2];
    const float* l1_bih = (const float*)d_in[3];
    const float* l1_bhh = (const float*)d_in[4];
    const float* fc1_W  = (const float*)d_in[5];
    const float* fc1_b  = (const float*)d_in[6];
    const float* fc2_W  = (const float*)d_in[7];
    const float* fc2_b  = (const float*)d_in[8];
    const float* fc3_W  = (const float*)d_in[9];
    const float* fc3_b  = (const float*)d_in[10];
    const float* fc4_W  = (const float*)d_in[11];
    const float* fc4_b  = (const float*)d_in[12];
    const float* l2_Wih = (const float*)d_in[13];
    const float* l2_Whh = (const float*)d_in[14];
    const float* l2_bih = (const float*)d_in[15];
    const float* l2_bhh = (const float*)d_in[16];
    const float* pi_W   = (const float*)d_in[17];
    const float* pi_b   = (const float*)d_in[18];
    float* out = (float*)d_out;

    float *c1, *c2, *h1f, *h2f, *badd1, *m1, *m2, *m3, *m4, *pre2;
    __half *h1hi, *h1lo, *h2hi, *h2lo;
    __half *w1hi, *w1lo, *w2hi, *w2lo, *wx1hi, *wx1lo, *wx2hi, *wx2lo, *xshi, *xslo;
    cudaGetSymbolAddress((void**)&c1, g_c1);
    cudaGetSymbolAddress((void**)&c2, g_c2);
    cudaGetSymbolAddress((void**)&h1f, g_h1f);
    cudaGetSymbolAddress((void**)&h2f, g_h2f);
    cudaGetSymbolAddress((void**)&h1hi, g_h1hi);
    cudaGetSymbolAddress((void**)&h1lo, g_h1lo);
    cudaGetSymbolAddress((void**)&h2hi, g_h2hi);
    cudaGetSymbolAddress((void**)&h2lo, g_h2lo);
    cudaGetSymbolAddress((void**)&w1hi, g_w1hi);
    cudaGetSymbolAddress((void**)&w1lo, g_w1lo);
    cudaGetSymbolAddress((void**)&w2hi, g_w2hi);
    cudaGetSymbolAddress((void**)&w2lo, g_w2lo);
    cudaGetSymbolAddress((void**)&wx1hi, g_wx1hi);
    cudaGetSymbolAddress((void**)&wx1lo, g_wx1lo);
    cudaGetSymbolAddress((void**)&wx2hi, g_wx2hi);
    cudaGetSymbolAddress((void**)&wx2lo, g_wx2lo);
    cudaGetSymbolAddress((void**)&xshi, g_xshi);
    cudaGetSymbolAddress((void**)&xslo, g_xslo);
    cudaGetSymbolAddress((void**)&badd1, g_badd1);
    cudaGetSymbolAddress((void**)&m1, g_m1);
    cudaGetSymbolAddress((void**)&m2, g_m2);
    cudaGetSymbolAddress((void**)&m3, g_m3);
    cudaGetSymbolAddress((void**)&m4, g_m4);
    cudaGetSymbolAddress((void**)&pre2, g_pre2);

    const int HB = Bsz * Hn;

    // ---- prep ----
    zero_states_kernel<<<(HB + 255) / 256, 256>>>();
    prep_w_kernel<<<(Gn * Hn + 255) / 256, 256>>>(l1_Whh, l1_Wih, l1_bih, l1_bhh, l2_Whh, l2_Wih);
    prep_x_kernel<<<(Vn * Bsz * 16 + 255) / 256, 256>>>(state);

    dim3 tgrid(Gn / 128, Bsz / 64);   // 8 x 64 = 512 CTAs

    // ---- LSTM1 scan ----
    for (int v = 0; v < Vn; v++) {
        int pi_ = v & 1, po = (v + 1) & 1;
        if (v < Vn - 1) {
            lstm_step_mma<0, 0, 1><<<tgrid, 256>>>(
                h1hi + pi_ * HB, h1lo + pi_ * HB,
                w1hi, w1lo, wx1hi, wx1lo,
                xshi + v * (Bsz * 16), xslo + v * (Bsz * 16),
                badd1, c1, h1f,
                h1hi + po * HB, h1lo + po * HB);
        } else {
            lstm_step_mma<0, 1, 0><<<tgrid, 256>>>(
                h1hi + pi_ * HB, h1lo + pi_ * HB,
                w1hi, w1lo, wx1hi, wx1lo,
                xshi + v * (Bsz * 16), xslo + v * (Bsz * 16),
                badd1, c1, h1f,
                h1hi + po * HB, h1lo + po * HB);
        }
    }

    // ---- MLP stack ----
    gemm3<1, 0, 1><<<dim3(1024 / 128, 32), 256>>>(h1f, Hn, fc1_W, Hn, Hn, fc1_b, nullptr, m1, 1024);
    gemm3<1, 0, 1><<<dim3(1024 / 128, 32), 256>>>(m1, 1024, fc2_W, 1024, 1024, fc2_b, nullptr, m2, 1024);
    gemm3<1, 0, 1><<<dim3(512 / 128, 32), 256>>>(m2, 1024, fc3_W, 1024, 1024, fc3_b, nullptr, m3, 512);
    gemm3<1, 0, 1><<<dim3(256 / 128, 32), 256>>>(m3, 512, fc4_W, 512, 512, fc4_b, nullptr, m4, 256);

    // ---- pre2 ----
    gemm3<0, 1, 0><<<dim3(Gn / 128, 32), 256>>>(m4, 256, l2_Wih + 15, 271, 256, l2_bih, l2_bhh, pre2, Gn);

    // ---- LSTM2 scan + pi head ----
    for (int v = 0; v < Vn; v++) {
        int pi_ = v & 1, po = (v + 1) & 1;
        if (v < Vn - 1) {
            lstm_step_mma<1, 1, 1><<<tgrid, 256>>>(
                h2hi + pi_ * HB, h2lo + pi_ * HB,
                w2hi, w2lo, wx2hi, wx2lo,
                xshi + v * (Bsz * 16), xslo + v * (Bsz * 16),
                pre2, c2, h2f,
                h2hi + po * HB, h2lo + po * HB);
        } else {
            lstm_step_mma<1, 1, 0><<<tgrid, 256>>>(
                h2hi + pi_ * HB, h2lo + pi_ * HB,
                w2hi, w2lo, wx2hi, wx2lo,
                xshi + v * (Bsz * 16), xslo + v * (Bsz * 16),
                pre2, c2, h2f,
                h2hi + po * HB, h2lo + po * HB);
        }
        pi_kernel<<<Bsz / 8, 256>>>(h2f, pi_W, pi_b, out, v);
    }
}

// round 13
// speedup vs baseline: 1.6172x; 1.6172x over previous
#include <cuda_runtime.h>

// Problem constants
#define Bsz 4096
#define Vn  50
#define Fn  15
#define Hn  256
#define Gn  1024   // 4*H

// ---------------- scratch (static device globals; no allocation) ----------
__device__ float g_h1a[Bsz * Hn];
__device__ float g_h1b[Bsz * Hn];
__device__ float g_c1 [Bsz * Hn];
__device__ float g_h2a[Bsz * Hn];
__device__ float g_h2b[Bsz * Hn];
__device__ float g_c2 [Bsz * Hn];
__device__ float g_m1[Bsz * 1024];
__device__ float g_m2[Bsz * 1024];
__device__ float g_m3[Bsz * 512];
__device__ float g_m4[Bsz * 256];
__device__ float g_pre2[Bsz * Gn];

typedef unsigned long long ull;

__device__ __forceinline__ void dup2(ull& d, float s) {
    asm("mov.b64 %0,{%1,%1};" : "=l"(d) : "f"(s));
}
__device__ __forceinline__ void ffma2(ull& d, ull a, ull b) {
    asm("fma.rn.f32x2 %0,%1,%2,%0;" : "+l"(d) : "l"(a), "l"(b));
}
__device__ __forceinline__ float2 u2f(ull u) {
    float2 f; asm("mov.b64 {%0,%1},%2;" : "=f"(f.x), "=f"(f.y) : "l"(u)); return f;
}
// Fast-math gates — VALIDATED in round 11 (rel_err 7.0e-6 end-to-end through
// both 50-step scans). Round-2's 4.5e-3 was the h-race, not __expf.
__device__ __forceinline__ float fsig(float x) {
    return __fdividef(1.0f, 1.0f + __expf(-x));
}
__device__ __forceinline__ float ftanh(float x) {
    return 1.0f - __fdividef(2.0f, __expf(2.0f * x) + 1.0f);
}

// ---------------- zero the recurrent states --------------------------------
__global__ void zero_states_kernel() {
    int idx = blockIdx.x * blockDim.x + threadIdx.x;
    if (idx < Bsz * Hn) {
        g_h1a[idx] = 0.f; g_c1[idx] = 0.f;
        g_h2a[idx] = 0.f; g_c2[idx] = 0.f;
    }
}

// ---------------- fused SGEMM (f32x2, quadrant microtile, K-tile 16) --------
// Block tile 128x128, 256 threads. Thread (tx,ty) owns
//   cols {n0+4tx..+3} U {n0+64+4tx..+3},  rows {m0+4ty..+3} U {m0+64+4ty..+3}
// -> conflict-free LDS.128 for B, broadcast A.
// REMAP: weight row = ((n&3)<<8)|(n>>2): each 4-col quadrant = one hidden
//        unit's {i,f,g,o}.
// EPI: 0 = bias store, 1 = relu store, 2 = LSTM cell update (fast-math gates)
// W4:  ldw%4==0 and 16B-aligned -> float4 W loads
template <int EPI, int REMAP, int W4>
__global__ void __launch_bounds__(256, 2) gemm3(
    const float* __restrict__ A,  int lda,
    const float* __restrict__ W,  int ldw, int K,
    const float* __restrict__ A2, int lda2,
    const float* __restrict__ W2, int ldw2, int K2,
    const float* __restrict__ b1, const float* __restrict__ b2,
    const float* __restrict__ addmat,
    float* __restrict__ C, int N,
    float* __restrict__ cSt)
{
    __shared__ float As[2][16][128];
    __shared__ float Bs[2][16][128];

    const int tid = threadIdx.x;
    const int tx = tid & 15;
    const int ty = tid >> 4;
    const int m0 = blockIdx.y * 128;
    const int n0 = blockIdx.x * 128;

    const int lr = tid >> 1;        // 0..127
    const int lc = (tid & 1) * 8;   // 0 or 8
    const int gn = n0 + lr;
    const int wrow = REMAP ? (((gn & 3) << 8) | (gn >> 2)) : gn;
    const float* Ap = A + (size_t)(m0 + lr) * lda + lc;
    const float* Wp = W + (size_t)wrow * ldw + lc;

    ull acc[8][4];
#pragma unroll
    for (int i = 0; i < 8; i++)
#pragma unroll
        for (int j = 0; j < 4; j++) acc[i][j] = 0ull;

    // ---- preload stage 0 ----
    {
        float4 a0 = *(const float4*)Ap;
        float4 a1 = *(const float4*)(Ap + 4);
        float4 w0, w1;
        if (W4) { w0 = *(const float4*)Wp; w1 = *(const float4*)(Wp + 4); }
        else {
            w0 = make_float4(Wp[0], Wp[1], Wp[2], Wp[3]);
            w1 = make_float4(Wp[4], Wp[5], Wp[6], Wp[7]);
        }
        As[0][lc + 0][lr] = a0.x; As[0][lc + 1][lr] = a0.y;
        As[0][lc + 2][lr] = a0.z; As[0][lc + 3][lr] = a0.w;
        As[0][lc + 4][lr] = a1.x; As[0][lc + 5][lr] = a1.y;
        As[0][lc + 6][lr] = a1.z; As[0][lc + 7][lr] = a1.w;
        Bs[0][lc + 0][lr] = w0.x; Bs[0][lc + 1][lr] = w0.y;
        Bs[0][lc + 2][lr] = w0.z; Bs[0][lc + 3][lr] = w0.w;
        Bs[0][lc + 4][lr] = w1.x; Bs[0][lc + 5][lr] = w1.y;
        Bs[0][lc + 6][lr] = w1.z; Bs[0][lc + 7][lr] = w1.w;
    }
    __syncthreads();

    int cur = 0;
    for (int k0 = 0; k0 < K; k0 += 16) {
        const bool more = (k0 + 16) < K;
        float4 pa0, pa1, pw0, pw1;
        if (more) {
            pa0 = *(const float4*)(Ap + k0 + 16);
            pa1 = *(const float4*)(Ap + k0 + 20);
            const float* wq = Wp + k0 + 16;
            if (W4) { pw0 = *(const float4*)wq; pw1 = *(const float4*)(wq + 4); }
            else {
                pw0 = make_float4(wq[0], wq[1], wq[2], wq[3]);
                pw1 = make_float4(wq[4], wq[5], wq[6], wq[7]);
            }
        }
#pragma unroll
        for (int kk = 0; kk < 16; kk++) {
            float4 a0 = *(const float4*)&As[cur][kk][ty * 4];
            float4 a1 = *(const float4*)&As[cur][kk][64 + ty * 4];
            ulonglong2 bq0 = *(const ulonglong2*)&Bs[cur][kk][tx * 4];
            ulonglong2 bq1 = *(const ulonglong2*)&Bs[cur][kk][64 + tx * 4];
            float ar[8] = {a0.x, a0.y, a0.z, a0.w, a1.x, a1.y, a1.z, a1.w};
#pragma unroll
            for (int i = 0; i < 8; i++) {
                ull aa; dup2(aa, ar[i]);
                ffma2(acc[i][0], aa, bq0.x);
                ffma2(acc[i][1], aa, bq0.y);
                ffma2(acc[i][2], aa, bq1.x);
                ffma2(acc[i][3], aa, bq1.y);
            }
        }
        if (more) {
            int nx = cur ^ 1;
            As[nx][lc + 0][lr] = pa0.x; As[nx][lc + 1][lr] = pa0.y;
            As[nx][lc + 2][lr] = pa0.z; As[nx][lc + 3][lr] = pa0.w;
            As[nx][lc + 4][lr] = pa1.x; As[nx][lc + 5][lr] = pa1.y;
            As[nx][lc + 6][lr] = pa1.z; As[nx][lc + 7][lr] = pa1.w;
            Bs[nx][lc + 0][lr] = pw0.x; Bs[nx][lc + 1][lr] = pw0.y;
            Bs[nx][lc + 2][lr] = pw0.z; Bs[nx][lc + 3][lr] = pw0.w;
            Bs[nx][lc + 4][lr] = pw1.x; Bs[nx][lc + 5][lr] = pw1.y;
            Bs[nx][lc + 6][lr] = pw1.z; Bs[nx][lc + 7][lr] = pw1.w;
        }
        __syncthreads();
        cur ^= 1;
    }

    // ---- small-K tail (x_v @ Wih_x.T, K2 <= 15) ----
    if (K2 > 0) {
        float (*Ta)[128] = (float(*)[128]) & As[0][0][0];
        float (*Tb)[128] = (float(*)[128]) & Bs[0][0][0];
        for (int idx = tid; idx < 128 * K2; idx += 256) {
            int m = idx & 127;
            int k = idx >> 7;
            Ta[k][m] = A2[(size_t)(m0 + m) * lda2 + k];
            int g2 = n0 + m;
            int wr2 = REMAP ? (((g2 & 3) << 8) | (g2 >> 2)) : g2;
            Tb[k][m] = W2[(size_t)wr2 * ldw2 + k];
        }
        __syncthreads();
        for (int kk = 0; kk < K2; kk++) {
            float4 a0 = *(const float4*)&Ta[kk][ty * 4];
            float4 a1 = *(const float4*)&Ta[kk][64 + ty * 4];
            ulonglong2 bq0 = *(const ulonglong2*)&Tb[kk][tx * 4];
            ulonglong2 bq1 = *(const ulonglong2*)&Tb[kk][64 + tx * 4];
            float ar[8] = {a0.x, a0.y, a0.z, a0.w, a1.x, a1.y, a1.z, a1.w};
#pragma unroll
            for (int i = 0; i < 8; i++) {
                ull aa; dup2(aa, ar[i]);
                ffma2(acc[i][0], aa, bq0.x);
                ffma2(acc[i][1], aa, bq0.y);
                ffma2(acc[i][2], aa, bq1.x);
                ffma2(acc[i][3], aa, bq1.y);
            }
        }
    }

    // ---- epilogue ----
    float add[8];
    if (EPI != 2 || addmat == nullptr) {
#pragma unroll
        for (int j = 0; j < 8; j++) {
            int n = n0 + ((j < 4) ? (4 * tx + j) : (64 + 4 * tx + (j - 4)));
            int rn = REMAP ? (((n & 3) << 8) | (n >> 2)) : n;
            float t = 0.f;
            if (b1) t += b1[rn];
            if (b2) t += b2[rn];
            add[j] = t;
        }
    }

    if (EPI == 2) {
        // quadrant q gives hidden unit hu_q = n0/4 + 16q + tx, gates j=0..3
        const int hu0 = (n0 >> 2) + tx;
        const int hu1 = hu0 + 16;
#pragma unroll
        for (int i = 0; i < 8; i++) {
            int m = m0 + ((i < 4) ? (4 * ty + i) : (64 + 4 * ty + (i - 4)));
            float g[8];
#pragma unroll
            for (int j4 = 0; j4 < 4; j4++) {
                float2 f = u2f(acc[i][j4]);
                g[2 * j4] = f.x; g[2 * j4 + 1] = f.y;
            }
            if (addmat) {
                float4 p0 = *(const float4*)(addmat + (size_t)m * Gn + n0 + 4 * tx);
                float4 p1 = *(const float4*)(addmat + (size_t)m * Gn + n0 + 64 + 4 * tx);
                g[0] += p0.x; g[1] += p0.y; g[2] += p0.z; g[3] += p0.w;
                g[4] += p1.x; g[5] += p1.y; g[6] += p1.z; g[7] += p1.w;
            } else {
#pragma unroll
                for (int j = 0; j < 8; j++) g[j] += add[j];
            }
            size_t c0i = (size_t)m * Hn + hu0;
            size_t c1i = (size_t)m * Hn + hu1;
            {
                float iv = fsig(g[0]), fv = fsig(g[1]);
                float gv = ftanh(g[2]), ov = fsig(g[3]);
                float cn = fv * cSt[c0i] + iv * gv;
                cSt[c0i] = cn;
                C[c0i] = ov * ftanh(cn);
            }
            {
                float iv = fsig(g[4]), fv = fsig(g[5]);
                float gv = ftanh(g[6]), ov = fsig(g[7]);
                float cn = fv * cSt[c1i] + iv * gv;
                cSt[c1i] = cn;
                C[c1i] = ov * ftanh(cn);
            }
        }
    } else {
#pragma unroll
        for (int i = 0; i < 8; i++) {
            int m = m0 + ((i < 4) ? (4 * ty + i) : (64 + 4 * ty + (i - 4)));
            float o[8];
#pragma unroll
            for (int j4 = 0; j4 < 4; j4++) {
                float2 f = u2f(acc[i][j4]);
                o[2 * j4]     = f.x + add[2 * j4];
                o[2 * j4 + 1] = f.y + add[2 * j4 + 1];
            }
            if (EPI == 1) {
#pragma unroll
                for (int j = 0; j < 8; j++) o[j] = fmaxf(o[j], 0.f);
            }
            *(float4*)(C + (size_t)m * N + n0 + 4 * tx)      = make_float4(o[0], o[1], o[2], o[3]);
            *(float4*)(C + (size_t)m * N + n0 + 64 + 4 * tx) = make_float4(o[4], o[5], o[6], o[7]);
        }
    }
}

// ---------------- pi head: out[b][v] = tanh(h2[b]·piW + pib) ----------------
__global__ void pi_kernel(const float* __restrict__ h2,
                          const float* __restrict__ piW,
                          const float* __restrict__ pib,
                          float* __restrict__ out, int v) {
    int gw = (blockIdx.x * blockDim.x + threadIdx.x) >> 5;
    int lane = threadIdx.x & 31;
    if (gw >= Bsz) return;
    const float* hr = h2 + (size_t)gw * Hn;
    float s = 0.f;
#pragma unroll
    for (int k = lane; k < Hn; k += 32) s += hr[k] * piW[k];
#pragma unroll
    for (int off = 16; off > 0; off >>= 1)
        s += __shfl_down_sync(0xffffffffu, s, off);
    if (lane == 0)
        out[(size_t)gw * Vn + v] = ftanh(s + pib[0]);
}

// ---------------- launch ----------------------------------------------------
extern "C" void kernel_launch(void* const* d_in, const int* in_sizes, int n_in,
                              void* d_out, int out_size) {
    const float* state  = (const float*)d_in[0];   // [4096, 750]
    const float* l1_Wih = (const float*)d_in[1];   // [1024, 15]
    const float* l1_Whh = (const float*)d_in[2];   // [1024, 256]
    const float* l1_bih = (const float*)d_in[3];
    const float* l1_bhh = (const float*)d_in[4];
    const float* fc1_W  = (const float*)d_in[5];   // [1024, 256]
    const float* fc1_b  = (const float*)d_in[6];
    const float* fc2_W  = (const float*)d_in[7];   // [1024, 1024]
    const float* fc2_b  = (const float*)d_in[8];
    const float* fc3_W  = (const float*)d_in[9];   // [512, 1024]
    const float* fc3_b  = (const float*)d_in[10];
    const float* fc4_W  = (const float*)d_in[11];  // [256, 512]
    const float* fc4_b  = (const float*)d_in[12];
    const float* l2_Wih = (const float*)d_in[13];  // [1024, 271]
    const float* l2_Whh = (const float*)d_in[14];  // [1024, 256]
    const float* l2_bih = (const float*)d_in[15];
    const float* l2_bhh = (const float*)d_in[16];
    const float* pi_W   = (const float*)d_in[17];  // [1, 256]
    const float* pi_b   = (const float*)d_in[18];  // [1]
    float* out = (float*)d_out;                    // [4096, 50]

    float *h1a, *h1b, *c1, *h2a, *h2b, *c2, *m1, *m2, *m3, *m4, *pre2;
    cudaGetSymbolAddress((void**)&h1a, g_h1a);
    cudaGetSymbolAddress((void**)&h1b, g_h1b);
    cudaGetSymbolAddress((void**)&c1,  g_c1);
    cudaGetSymbolAddress((void**)&h2a, g_h2a);
    cudaGetSymbolAddress((void**)&h2b, g_h2b);
    cudaGetSymbolAddress((void**)&c2,  g_c2);
    cudaGetSymbolAddress((void**)&m1, g_m1);
    cudaGetSymbolAddress((void**)&m2, g_m2);
    cudaGetSymbolAddress((void**)&m3, g_m3);
    cudaGetSymbolAddress((void**)&m4, g_m4);
    cudaGetSymbolAddress((void**)&pre2, g_pre2);

    zero_states_kernel<<<(Bsz * Hn + 255) / 256, 256>>>();

    dim3 sgrid(Gn / 128, Bsz / 128);   // 8 x 32

    // ---- LSTM1 scan (fused gate GEMM + cell update), ping-pong h ----
    for (int v = 0; v < Vn; v++) {
        const float* hin  = (v & 1) ? h1b : h1a;
        float*       hout = (v & 1) ? h1a : h1b;
        gemm3<2, 1, 1><<<sgrid, 256>>>(
            hin, Hn, l1_Whh, Hn, Hn,
            state + v * Fn, Vn * Fn, l1_Wih, Fn, Fn,
            l1_bih, l1_bhh, nullptr,
            hout, Gn, c1);
    }
    const float* h1fin = (Vn & 1) ? h1b : h1a;

    // ---- MLP stack (relu) ----
    gemm3<1, 0, 1><<<dim3(1024 / 128, 32), 256>>>(
        h1fin, Hn, fc1_W, Hn, Hn,
        nullptr, 0, nullptr, 0, 0,
        fc1_b, nullptr, nullptr, m1, 1024, nullptr);
    gemm3<1, 0, 1><<<dim3(1024 / 128, 32), 256>>>(
        m1, 1024, fc2_W, 1024, 1024,
        nullptr, 0, nullptr, 0, 0,
        fc2_b, nullptr, nullptr, m2, 1024, nullptr);
    gemm3<1, 0, 1><<<dim3(512 / 128, 32), 256>>>(
        m2, 1024, fc3_W, 1024, 1024,
        nullptr, 0, nullptr, 0, 0,
        fc3_b, nullptr, nullptr, m3, 512, nullptr);
    gemm3<1, 0, 1><<<dim3(256 / 128, 32), 256>>>(
        m3, 512, fc4_W, 512, 512,
        nullptr, 0, nullptr, 0, 0,
        fc4_b, nullptr, nullptr, m4, 256, nullptr);

    // ---- pre2 = m4 @ Wih2[:,15:].T + bih + bhh  (REMAPPED quadrant layout) --
    gemm3<0, 1, 0><<<sgrid, 256>>>(
        m4, 256, l2_Wih + 15, 271, 256,
        nullptr, 0, nullptr, 0, 0,
        l2_bih, l2_bhh, nullptr, pre2, Gn, nullptr);

    // ---- LSTM2 scan (fused) + pi head, ping-pong h ----
    for (int v = 0; v < Vn; v++) {
        const float* hin  = (v & 1) ? h2b : h2a;
        float*       hout = (v & 1) ? h2a : h2b;
        gemm3<2, 1, 1><<<sgrid, 256>>>(
            hin, Hn, l2_Whh, Hn, Hn,
            state + v * Fn, Vn * Fn, l2_Wih, 271, Fn,
            nullptr, nullptr, pre2,
            hout, Gn, c2);
        pi_kernel<<<Bsz / 8, 256>>>(hout, pi_W, pi_b, out, v);
    }
}